// round 1
// baseline (speedup 1.0000x reference)
#include <cuda_runtime.h>
#include <math.h>

#define TSEQ 2048
#define NH 16
#define NB 4
#define DHD 64
#define BHT (NB*NH)          // 64
#define DMODEL 1024
#define MROWS (NB*TSEQ)      // 8192

// Scratch (device globals: allocation-free rule)
__device__ float g_q[BHT*TSEQ*DHD];
__device__ float g_k[BHT*TSEQ*DHD];
__device__ float g_v[BHT*TSEQ*DHD];
__device__ float g_o[MROWS*DMODEL];

__device__ __forceinline__ unsigned f2t(float x){
    unsigned u; asm("cvt.rna.tf32.f32 %0, %1;" : "=r"(u) : "f"(x)); return u;
}

__device__ __forceinline__ void mma8(float* d, const unsigned* a, unsigned b0, unsigned b1){
    asm volatile("mma.sync.aligned.m16n8k8.row.col.f32.tf32.tf32.f32 "
        "{%0,%1,%2,%3},{%4,%5,%6,%7},{%8,%9},{%0,%1,%2,%3};"
        : "+f"(d[0]),"+f"(d[1]),"+f"(d[2]),"+f"(d[3])
        : "r"(a[0]),"r"(a[1]),"r"(a[2]),"r"(a[3]),"r"(b0),"r"(b1));
}

__device__ __forceinline__ void qkv_store(int row, int col, float v){
    int i = col >> 10;            // 0:q 1:k 2:v
    int r = col & 1023;
    int h = r >> 6, d = r & 63;
    int b = row >> 11, t = row & 2047;
    float* dst = (i == 0) ? g_q : ((i == 1) ? g_k : g_v);
    dst[(((b<<4)+h)*TSEQ + t)*DHD + d] = v;
}

// C(M x NCOLS) = A(M x 1024) * B(1024 x NCOLS). MODE 0: scatter to q/k/v. MODE 1: +bias -> Cout
template<int NCOLS, int MODE>
__global__ __launch_bounds__(256)
void gemm_tf32(const float* __restrict__ A, const float* __restrict__ Bm,
               const float* __restrict__ bias, float* __restrict__ Cout)
{
    __shared__ unsigned As[2][16][132];
    __shared__ unsigned Bs[2][16][132];
    const int tid  = threadIdx.x;
    const int row0 = blockIdx.y * 128;
    const int col0 = blockIdx.x * 128;
    const int warp = tid >> 5, lane = tid & 31;
    const int g = lane >> 2, tg = lane & 3;
    const int wm = (warp & 3) * 32, wn = (warp >> 2) * 64;

    if (MODE == 1) A = g_o;

    float acc[2][8][4];
    #pragma unroll
    for (int mi = 0; mi < 2; mi++)
        #pragma unroll
        for (int ni = 0; ni < 8; ni++)
            #pragma unroll
            for (int e = 0; e < 4; e++) acc[mi][ni][e] = 0.f;

    const int ar0 = tid >> 2, akq = tid & 3;     // A: rows ar0, ar0+64; k-quad akq
    const int bkr = tid >> 5, bcq = tid & 31;    // B: k-rows bkr, bkr+8; col-quad bcq

    float4 fa0, fa1, fb0, fb1;
    auto FETCH = [&](int kt){
        fa0 = *(const float4*)(A + (size_t)(row0 + ar0     )*1024 + kt*16 + akq*4);
        fa1 = *(const float4*)(A + (size_t)(row0 + ar0 + 64)*1024 + kt*16 + akq*4);
        fb0 = *(const float4*)(Bm + (size_t)(kt*16 + bkr    )*NCOLS + col0 + bcq*4);
        fb1 = *(const float4*)(Bm + (size_t)(kt*16 + bkr + 8)*NCOLS + col0 + bcq*4);
    };
    auto STORE = [&](int buf){
        As[buf][akq*4+0][ar0]      = f2t(fa0.x);
        As[buf][akq*4+1][ar0]      = f2t(fa0.y);
        As[buf][akq*4+2][ar0]      = f2t(fa0.z);
        As[buf][akq*4+3][ar0]      = f2t(fa0.w);
        As[buf][akq*4+0][ar0+64]   = f2t(fa1.x);
        As[buf][akq*4+1][ar0+64]   = f2t(fa1.y);
        As[buf][akq*4+2][ar0+64]   = f2t(fa1.z);
        As[buf][akq*4+3][ar0+64]   = f2t(fa1.w);
        uint4 u0; u0.x=f2t(fb0.x); u0.y=f2t(fb0.y); u0.z=f2t(fb0.z); u0.w=f2t(fb0.w);
        uint4 u1; u1.x=f2t(fb1.x); u1.y=f2t(fb1.y); u1.z=f2t(fb1.z); u1.w=f2t(fb1.w);
        *(uint4*)&Bs[buf][bkr  ][bcq*4] = u0;
        *(uint4*)&Bs[buf][bkr+8][bcq*4] = u1;
    };
    auto COMPUTE = [&](int buf){
        #pragma unroll
        for (int ks = 0; ks < 2; ks++){
            const int k0 = ks * 8;
            unsigned af[2][4], bf[8][2];
            #pragma unroll
            for (int mi = 0; mi < 2; mi++){
                af[mi][0] = As[buf][k0+tg  ][wm+mi*16+g  ];
                af[mi][1] = As[buf][k0+tg  ][wm+mi*16+g+8];
                af[mi][2] = As[buf][k0+tg+4][wm+mi*16+g  ];
                af[mi][3] = As[buf][k0+tg+4][wm+mi*16+g+8];
            }
            #pragma unroll
            for (int ni = 0; ni < 8; ni++){
                bf[ni][0] = Bs[buf][k0+tg  ][wn+ni*8+g];
                bf[ni][1] = Bs[buf][k0+tg+4][wn+ni*8+g];
            }
            #pragma unroll
            for (int mi = 0; mi < 2; mi++)
                #pragma unroll
                for (int ni = 0; ni < 8; ni++)
                    mma8(acc[mi][ni], af[mi], bf[ni][0], bf[ni][1]);
        }
    };

    FETCH(0); STORE(0); __syncthreads();
    for (int kt = 0; kt < 64; ++kt){
        int cur = kt & 1;
        if (kt < 63) FETCH(kt + 1);
        COMPUTE(cur);
        if (kt < 63) STORE(cur ^ 1);
        __syncthreads();
    }

    #pragma unroll
    for (int mi = 0; mi < 2; mi++){
        #pragma unroll
        for (int ni = 0; ni < 8; ni++){
            int row = row0 + wm + mi*16 + g;
            int col = col0 + wn + ni*8 + 2*tg;
            if (MODE == 0){
                qkv_store(row,   col,   acc[mi][ni][0]);
                qkv_store(row,   col+1, acc[mi][ni][1]);
                qkv_store(row+8, col,   acc[mi][ni][2]);
                qkv_store(row+8, col+1, acc[mi][ni][3]);
            } else {
                Cout[(size_t)row*1024 + col]         = acc[mi][ni][0] + bias[col];
                Cout[(size_t)row*1024 + col + 1]     = acc[mi][ni][1] + bias[col+1];
                Cout[(size_t)(row+8)*1024 + col]     = acc[mi][ni][2] + bias[col];
                Cout[(size_t)(row+8)*1024 + col + 1] = acc[mi][ni][3] + bias[col+1];
            }
        }
    }
}

// XOR swizzles over stride-64 tiles (conflict-free fragment access, 48KB total)
#define KSW(r,c) ((r)*64 + ((c) ^ ((((r)&7))<<2)))
#define VSW(r,c) ((r)*64 + ((c) ^ ((((r)&3))<<3)))
#define PSW(r,c) ((r)*64 + ((c) ^ ((((r)&7))<<2)))

// Flash attention, causal. grid(32 q-tiles, 64 bh), 128 threads (4 warps x 16 q rows)
__global__ __launch_bounds__(128)
void attn_kernel()
{
    __shared__ unsigned Ks[64*64];
    __shared__ unsigned Vs[64*64];
    __shared__ unsigned Ps[64*64];

    const int qt = blockIdx.x, bh = blockIdx.y;
    const int tid = threadIdx.x, warp = tid >> 5, lane = tid & 31;
    const int g = lane >> 2, tg = lane & 3;
    const float* Qp = g_q + (size_t)bh * TSEQ * DHD;
    const float* Kp = g_k + (size_t)bh * TSEQ * DHD;
    const float* Vp = g_v + (size_t)bh * TSEQ * DHD;
    const int qrow0 = qt*64 + warp*16;

    // Q fragments (pre-scaled by Dh^-0.5 = 0.125), row-major A frags over 8 k-steps
    unsigned qa[8][4];
    #pragma unroll
    for (int ks = 0; ks < 8; ks++){
        int d = ks*8;
        qa[ks][0] = f2t(Qp[(size_t)(qrow0+g  )*DHD + d+tg  ] * 0.125f);
        qa[ks][1] = f2t(Qp[(size_t)(qrow0+g+8)*DHD + d+tg  ] * 0.125f);
        qa[ks][2] = f2t(Qp[(size_t)(qrow0+g  )*DHD + d+tg+4] * 0.125f);
        qa[ks][3] = f2t(Qp[(size_t)(qrow0+g+8)*DHD + d+tg+4] * 0.125f);
    }

    float o[8][4];
    #pragma unroll
    for (int ni = 0; ni < 8; ni++){ o[ni][0]=0.f; o[ni][1]=0.f; o[ni][2]=0.f; o[ni][3]=0.f; }
    float mrow0 = -1e30f, mrow1 = -1e30f, lrow0 = 0.f, lrow1 = 0.f;

    for (int kt = 0; kt <= qt; ++kt){
        const int kb = kt * 64;
        // load K,V tiles (tf32, swizzled)
        #pragma unroll
        for (int i = 0; i < 8; i++){
            int v = tid + i*128;
            int r = v >> 4, c4 = v & 15;
            float4 kv = *(const float4*)&Kp[(size_t)(kb+r)*DHD + c4*4];
            uint4 uk; uk.x=f2t(kv.x); uk.y=f2t(kv.y); uk.z=f2t(kv.z); uk.w=f2t(kv.w);
            *(uint4*)&Ks[KSW(r, c4*4)] = uk;
            float4 vv = *(const float4*)&Vp[(size_t)(kb+r)*DHD + c4*4];
            uint4 uv; uv.x=f2t(vv.x); uv.y=f2t(vv.y); uv.z=f2t(vv.z); uv.w=f2t(vv.w);
            *(uint4*)&Vs[VSW(r, c4*4)] = uv;
        }
        __syncthreads();

        // S = Q K^T
        float s[8][4];
        #pragma unroll
        for (int nt = 0; nt < 8; nt++){ s[nt][0]=0.f; s[nt][1]=0.f; s[nt][2]=0.f; s[nt][3]=0.f; }
        #pragma unroll
        for (int ks = 0; ks < 8; ks++){
            #pragma unroll
            for (int nt = 0; nt < 8; nt++){
                unsigned b0 = Ks[KSW(nt*8+g, ks*8+tg  )];
                unsigned b1 = Ks[KSW(nt*8+g, ks*8+tg+4)];
                mma8(s[nt], qa[ks], b0, b1);
            }
        }

        if (kt == qt){
            const int rb = warp*16 + g;
            #pragma unroll
            for (int nt = 0; nt < 8; nt++){
                int c = nt*8 + 2*tg;
                if (c   > rb  ) s[nt][0] = -1e30f;
                if (c+1 > rb  ) s[nt][1] = -1e30f;
                if (c   > rb+8) s[nt][2] = -1e30f;
                if (c+1 > rb+8) s[nt][3] = -1e30f;
            }
        }

        // online softmax (2 rows per thread: g and g+8)
        float mx0 = -1e30f, mx1 = -1e30f;
        #pragma unroll
        for (int nt = 0; nt < 8; nt++){
            mx0 = fmaxf(mx0, fmaxf(s[nt][0], s[nt][1]));
            mx1 = fmaxf(mx1, fmaxf(s[nt][2], s[nt][3]));
        }
        mx0 = fmaxf(mx0, __shfl_xor_sync(0xffffffffu, mx0, 1));
        mx0 = fmaxf(mx0, __shfl_xor_sync(0xffffffffu, mx0, 2));
        mx1 = fmaxf(mx1, __shfl_xor_sync(0xffffffffu, mx1, 1));
        mx1 = fmaxf(mx1, __shfl_xor_sync(0xffffffffu, mx1, 2));
        float mn0 = fmaxf(mrow0, mx0), mn1 = fmaxf(mrow1, mx1);
        float sc0 = __expf(mrow0 - mn0), sc1 = __expf(mrow1 - mn1);

        const int pr0 = warp*16 + g, pr1 = pr0 + 8;
        float sum0 = 0.f, sum1 = 0.f;
        #pragma unroll
        for (int nt = 0; nt < 8; nt++){
            float p00 = __expf(s[nt][0] - mn0);
            float p01 = __expf(s[nt][1] - mn0);
            float p10 = __expf(s[nt][2] - mn1);
            float p11 = __expf(s[nt][3] - mn1);
            sum0 += p00 + p01; sum1 += p10 + p11;
            int c = nt*8 + 2*tg;
            Ps[PSW(pr0, c  )] = f2t(p00);
            Ps[PSW(pr0, c+1)] = f2t(p01);
            Ps[PSW(pr1, c  )] = f2t(p10);
            Ps[PSW(pr1, c+1)] = f2t(p11);
        }
        sum0 += __shfl_xor_sync(0xffffffffu, sum0, 1);
        sum0 += __shfl_xor_sync(0xffffffffu, sum0, 2);
        sum1 += __shfl_xor_sync(0xffffffffu, sum1, 1);
        sum1 += __shfl_xor_sync(0xffffffffu, sum1, 2);
        lrow0 = lrow0 * sc0 + sum0;
        lrow1 = lrow1 * sc1 + sum1;
        mrow0 = mn0; mrow1 = mn1;
        #pragma unroll
        for (int nt = 0; nt < 8; nt++){
            o[nt][0] *= sc0; o[nt][1] *= sc0;
            o[nt][2] *= sc1; o[nt][3] *= sc1;
        }
        __syncwarp();

        // O += P V
        #pragma unroll
        for (int k2 = 0; k2 < 8; k2++){
            unsigned pa[4];
            pa[0] = Ps[PSW(pr0, k2*8+tg  )];
            pa[1] = Ps[PSW(pr1, k2*8+tg  )];
            pa[2] = Ps[PSW(pr0, k2*8+tg+4)];
            pa[3] = Ps[PSW(pr1, k2*8+tg+4)];
            #pragma unroll
            for (int nt = 0; nt < 8; nt++){
                unsigned b0 = Vs[VSW(k2*8+tg,   nt*8+g)];
                unsigned b1 = Vs[VSW(k2*8+tg+4, nt*8+g)];
                mma8(o[nt], pa, b0, b1);
            }
        }
        __syncthreads();
    }

    // epilogue: O /= l, write (B,T,D)
    float i0 = 1.f / lrow0, i1 = 1.f / lrow1;
    int b = bh >> 4, h = bh & 15;
    float* Op  = g_o + (size_t)(b*TSEQ + qrow0 + g)*DMODEL + h*64;
    float* Op8 = Op + (size_t)8*DMODEL;
    #pragma unroll
    for (int nt = 0; nt < 8; nt++){
        int d = nt*8 + 2*tg;
        Op [d]   = o[nt][0] * i0;
        Op [d+1] = o[nt][1] * i0;
        Op8[d]   = o[nt][2] * i1;
        Op8[d+1] = o[nt][3] * i1;
    }
}

extern "C" void kernel_launch(void* const* d_in, const int* in_sizes, int n_in,
                              void* d_out, int out_size)
{
    const float* x     = (const float*)d_in[0];
    const float* wqkv  = (const float*)d_in[1];
    const float* wproj = (const float*)d_in[2];
    const float* bproj = (const float*)d_in[3];
    float* out = (float*)d_out;

    gemm_tf32<3072, 0><<<dim3(24, 64), 256>>>(x, wqkv, nullptr, nullptr);
    attn_kernel<<<dim3(32, 64), 128>>>();
    gemm_tf32<1024, 1><<<dim3(8, 64), 256>>>(nullptr, wproj, bproj, out);
}

// round 2
// speedup vs baseline: 1.0007x; 1.0007x over previous
#include <cuda_runtime.h>
#include <math.h>

#define TSEQ 2048
#define NH 16
#define NB 4
#define DHD 64
#define BHT (NB*NH)          // 64
#define DMODEL 1024
#define MROWS (NB*TSEQ)      // 8192

// Scratch (device globals: allocation-free rule)
__device__ float g_q[BHT*TSEQ*DHD];
__device__ float g_k[BHT*TSEQ*DHD];
__device__ float g_v[BHT*TSEQ*DHD];
__device__ float g_o[MROWS*DMODEL];

__device__ __forceinline__ unsigned f2t(float x){
    unsigned u; asm("cvt.rna.tf32.f32 %0, %1;" : "=r"(u) : "f"(x)); return u;
}

__device__ __forceinline__ void mma8(float* d, const unsigned* a, unsigned b0, unsigned b1){
    asm volatile("mma.sync.aligned.m16n8k8.row.col.f32.tf32.tf32.f32 "
        "{%0,%1,%2,%3},{%4,%5,%6,%7},{%8,%9},{%0,%1,%2,%3};"
        : "+f"(d[0]),"+f"(d[1]),"+f"(d[2]),"+f"(d[3])
        : "r"(a[0]),"r"(a[1]),"r"(a[2]),"r"(a[3]),"r"(b0),"r"(b1));
}

__device__ __forceinline__ void qkv_store(int row, int col, float v){
    int i = col >> 10;            // 0:q 1:k 2:v
    int r = col & 1023;
    int h = r >> 6, d = r & 63;
    int b = row >> 11, t = row & 2047;
    float* dst = (i == 0) ? g_q : ((i == 1) ? g_k : g_v);
    dst[(((b<<4)+h)*TSEQ + t)*DHD + d] = v;
}

// C(M x NCOLS) = A(M x 1024) * B(1024 x NCOLS). MODE 0: scatter to q/k/v. MODE 1: +bias -> Cout
template<int NCOLS, int MODE>
__global__ __launch_bounds__(256)
void gemm_tf32(const float* __restrict__ A, const float* __restrict__ Bm,
               const float* __restrict__ bias, float* __restrict__ Cout)
{
    __shared__ unsigned As[2][16][132];
    __shared__ unsigned Bs[2][16][132];
    const int tid  = threadIdx.x;
    const int row0 = blockIdx.y * 128;
    const int col0 = blockIdx.x * 128;
    const int warp = tid >> 5, lane = tid & 31;
    const int g = lane >> 2, tg = lane & 3;
    const int wm = (warp & 3) * 32, wn = (warp >> 2) * 64;

    if (MODE == 1) A = g_o;

    float acc[2][8][4];
    #pragma unroll
    for (int mi = 0; mi < 2; mi++)
        #pragma unroll
        for (int ni = 0; ni < 8; ni++)
            #pragma unroll
            for (int e = 0; e < 4; e++) acc[mi][ni][e] = 0.f;

    const int ar0 = tid >> 2, akq = tid & 3;     // A: rows ar0, ar0+64; k-quad akq
    const int bkr = tid >> 5, bcq = tid & 31;    // B: k-rows bkr, bkr+8; col-quad bcq

    float4 fa0, fa1, fb0, fb1;
    auto FETCH = [&](int kt){
        fa0 = *(const float4*)(A + (size_t)(row0 + ar0     )*1024 + kt*16 + akq*4);
        fa1 = *(const float4*)(A + (size_t)(row0 + ar0 + 64)*1024 + kt*16 + akq*4);
        fb0 = *(const float4*)(Bm + (size_t)(kt*16 + bkr    )*NCOLS + col0 + bcq*4);
        fb1 = *(const float4*)(Bm + (size_t)(kt*16 + bkr + 8)*NCOLS + col0 + bcq*4);
    };
    auto STORE = [&](int buf){
        As[buf][akq*4+0][ar0]      = f2t(fa0.x);
        As[buf][akq*4+1][ar0]      = f2t(fa0.y);
        As[buf][akq*4+2][ar0]      = f2t(fa0.z);
        As[buf][akq*4+3][ar0]      = f2t(fa0.w);
        As[buf][akq*4+0][ar0+64]   = f2t(fa1.x);
        As[buf][akq*4+1][ar0+64]   = f2t(fa1.y);
        As[buf][akq*4+2][ar0+64]   = f2t(fa1.z);
        As[buf][akq*4+3][ar0+64]   = f2t(fa1.w);
        uint4 u0; u0.x=f2t(fb0.x); u0.y=f2t(fb0.y); u0.z=f2t(fb0.z); u0.w=f2t(fb0.w);
        uint4 u1; u1.x=f2t(fb1.x); u1.y=f2t(fb1.y); u1.z=f2t(fb1.z); u1.w=f2t(fb1.w);
        *(uint4*)&Bs[buf][bkr  ][bcq*4] = u0;
        *(uint4*)&Bs[buf][bkr+8][bcq*4] = u1;
    };
    auto COMPUTE = [&](int buf){
        #pragma unroll
        for (int ks = 0; ks < 2; ks++){
            const int k0 = ks * 8;
            unsigned af[2][4], bf[8][2];
            #pragma unroll
            for (int mi = 0; mi < 2; mi++){
                af[mi][0] = As[buf][k0+tg  ][wm+mi*16+g  ];
                af[mi][1] = As[buf][k0+tg  ][wm+mi*16+g+8];
                af[mi][2] = As[buf][k0+tg+4][wm+mi*16+g  ];
                af[mi][3] = As[buf][k0+tg+4][wm+mi*16+g+8];
            }
            #pragma unroll
            for (int ni = 0; ni < 8; ni++){
                bf[ni][0] = Bs[buf][k0+tg  ][wn+ni*8+g];
                bf[ni][1] = Bs[buf][k0+tg+4][wn+ni*8+g];
            }
            #pragma unroll
            for (int mi = 0; mi < 2; mi++)
                #pragma unroll
                for (int ni = 0; ni < 8; ni++)
                    mma8(acc[mi][ni], af[mi], bf[ni][0], bf[ni][1]);
        }
    };

    FETCH(0); STORE(0); __syncthreads();
    for (int kt = 0; kt < 64; ++kt){
        int cur = kt & 1;
        if (kt < 63) FETCH(kt + 1);
        COMPUTE(cur);
        if (kt < 63) STORE(cur ^ 1);
        __syncthreads();
    }

    #pragma unroll
    for (int mi = 0; mi < 2; mi++){
        #pragma unroll
        for (int ni = 0; ni < 8; ni++){
            int row = row0 + wm + mi*16 + g;
            int col = col0 + wn + ni*8 + 2*tg;
            if (MODE == 0){
                qkv_store(row,   col,   acc[mi][ni][0]);
                qkv_store(row,   col+1, acc[mi][ni][1]);
                qkv_store(row+8, col,   acc[mi][ni][2]);
                qkv_store(row+8, col+1, acc[mi][ni][3]);
            } else {
                Cout[(size_t)row*1024 + col]         = acc[mi][ni][0] + bias[col];
                Cout[(size_t)row*1024 + col + 1]     = acc[mi][ni][1] + bias[col+1];
                Cout[(size_t)(row+8)*1024 + col]     = acc[mi][ni][2] + bias[col];
                Cout[(size_t)(row+8)*1024 + col + 1] = acc[mi][ni][3] + bias[col+1];
            }
        }
    }
}

// XOR swizzles over stride-64 tiles (conflict-free fragment access, 48KB total)
#define KSW(r,c) ((r)*64 + ((c) ^ ((((r)&7))<<2)))
#define VSW(r,c) ((r)*64 + ((c) ^ ((((r)&3))<<3)))
#define PSW(r,c) ((r)*64 + ((c) ^ ((((r)&7))<<2)))

// Flash attention, causal. grid(32 q-tiles, 64 bh), 128 threads (4 warps x 16 q rows)
__global__ __launch_bounds__(128)
void attn_kernel()
{
    __shared__ unsigned Ks[64*64];
    __shared__ unsigned Vs[64*64];
    __shared__ unsigned Ps[64*64];

    const int qt = blockIdx.x, bh = blockIdx.y;
    const int tid = threadIdx.x, warp = tid >> 5, lane = tid & 31;
    const int g = lane >> 2, tg = lane & 3;
    const float* Qp = g_q + (size_t)bh * TSEQ * DHD;
    const float* Kp = g_k + (size_t)bh * TSEQ * DHD;
    const float* Vp = g_v + (size_t)bh * TSEQ * DHD;
    const int qrow0 = qt*64 + warp*16;

    // Q fragments (pre-scaled by Dh^-0.5 = 0.125), row-major A frags over 8 k-steps
    unsigned qa[8][4];
    #pragma unroll
    for (int ks = 0; ks < 8; ks++){
        int d = ks*8;
        qa[ks][0] = f2t(Qp[(size_t)(qrow0+g  )*DHD + d+tg  ] * 0.125f);
        qa[ks][1] = f2t(Qp[(size_t)(qrow0+g+8)*DHD + d+tg  ] * 0.125f);
        qa[ks][2] = f2t(Qp[(size_t)(qrow0+g  )*DHD + d+tg+4] * 0.125f);
        qa[ks][3] = f2t(Qp[(size_t)(qrow0+g+8)*DHD + d+tg+4] * 0.125f);
    }

    float o[8][4];
    #pragma unroll
    for (int ni = 0; ni < 8; ni++){ o[ni][0]=0.f; o[ni][1]=0.f; o[ni][2]=0.f; o[ni][3]=0.f; }
    float mrow0 = -1e30f, mrow1 = -1e30f, lrow0 = 0.f, lrow1 = 0.f;

    for (int kt = 0; kt <= qt; ++kt){
        const int kb = kt * 64;
        // load K,V tiles (tf32, swizzled)
        #pragma unroll
        for (int i = 0; i < 8; i++){
            int v = tid + i*128;
            int r = v >> 4, c4 = v & 15;
            float4 kv = *(const float4*)&Kp[(size_t)(kb+r)*DHD + c4*4];
            uint4 uk; uk.x=f2t(kv.x); uk.y=f2t(kv.y); uk.z=f2t(kv.z); uk.w=f2t(kv.w);
            *(uint4*)&Ks[KSW(r, c4*4)] = uk;
            float4 vv = *(const float4*)&Vp[(size_t)(kb+r)*DHD + c4*4];
            uint4 uv; uv.x=f2t(vv.x); uv.y=f2t(vv.y); uv.z=f2t(vv.z); uv.w=f2t(vv.w);
            *(uint4*)&Vs[VSW(r, c4*4)] = uv;
        }
        __syncthreads();

        // S = Q K^T
        float s[8][4];
        #pragma unroll
        for (int nt = 0; nt < 8; nt++){ s[nt][0]=0.f; s[nt][1]=0.f; s[nt][2]=0.f; s[nt][3]=0.f; }
        #pragma unroll
        for (int ks = 0; ks < 8; ks++){
            #pragma unroll
            for (int nt = 0; nt < 8; nt++){
                unsigned b0 = Ks[KSW(nt*8+g, ks*8+tg  )];
                unsigned b1 = Ks[KSW(nt*8+g, ks*8+tg+4)];
                mma8(s[nt], qa[ks], b0, b1);
            }
        }

        if (kt == qt){
            const int rb = warp*16 + g;
            #pragma unroll
            for (int nt = 0; nt < 8; nt++){
                int c = nt*8 + 2*tg;
                if (c   > rb  ) s[nt][0] = -1e30f;
                if (c+1 > rb  ) s[nt][1] = -1e30f;
                if (c   > rb+8) s[nt][2] = -1e30f;
                if (c+1 > rb+8) s[nt][3] = -1e30f;
            }
        }

        // online softmax (2 rows per thread: g and g+8)
        float mx0 = -1e30f, mx1 = -1e30f;
        #pragma unroll
        for (int nt = 0; nt < 8; nt++){
            mx0 = fmaxf(mx0, fmaxf(s[nt][0], s[nt][1]));
            mx1 = fmaxf(mx1, fmaxf(s[nt][2], s[nt][3]));
        }
        mx0 = fmaxf(mx0, __shfl_xor_sync(0xffffffffu, mx0, 1));
        mx0 = fmaxf(mx0, __shfl_xor_sync(0xffffffffu, mx0, 2));
        mx1 = fmaxf(mx1, __shfl_xor_sync(0xffffffffu, mx1, 1));
        mx1 = fmaxf(mx1, __shfl_xor_sync(0xffffffffu, mx1, 2));
        float mn0 = fmaxf(mrow0, mx0), mn1 = fmaxf(mrow1, mx1);
        float sc0 = __expf(mrow0 - mn0), sc1 = __expf(mrow1 - mn1);

        const int pr0 = warp*16 + g, pr1 = pr0 + 8;
        float sum0 = 0.f, sum1 = 0.f;
        #pragma unroll
        for (int nt = 0; nt < 8; nt++){
            float p00 = __expf(s[nt][0] - mn0);
            float p01 = __expf(s[nt][1] - mn0);
            float p10 = __expf(s[nt][2] - mn1);
            float p11 = __expf(s[nt][3] - mn1);
            sum0 += p00 + p01; sum1 += p10 + p11;
            int c = nt*8 + 2*tg;
            Ps[PSW(pr0, c  )] = f2t(p00);
            Ps[PSW(pr0, c+1)] = f2t(p01);
            Ps[PSW(pr1, c  )] = f2t(p10);
            Ps[PSW(pr1, c+1)] = f2t(p11);
        }
        sum0 += __shfl_xor_sync(0xffffffffu, sum0, 1);
        sum0 += __shfl_xor_sync(0xffffffffu, sum0, 2);
        sum1 += __shfl_xor_sync(0xffffffffu, sum1, 1);
        sum1 += __shfl_xor_sync(0xffffffffu, sum1, 2);
        lrow0 = lrow0 * sc0 + sum0;
        lrow1 = lrow1 * sc1 + sum1;
        mrow0 = mn0; mrow1 = mn1;
        #pragma unroll
        for (int nt = 0; nt < 8; nt++){
            o[nt][0] *= sc0; o[nt][1] *= sc0;
            o[nt][2] *= sc1; o[nt][3] *= sc1;
        }
        __syncwarp();

        // O += P V
        #pragma unroll
        for (int k2 = 0; k2 < 8; k2++){
            unsigned pa[4];
            pa[0] = Ps[PSW(pr0, k2*8+tg  )];
            pa[1] = Ps[PSW(pr1, k2*8+tg  )];
            pa[2] = Ps[PSW(pr0, k2*8+tg+4)];
            pa[3] = Ps[PSW(pr1, k2*8+tg+4)];
            #pragma unroll
            for (int nt = 0; nt < 8; nt++){
                unsigned b0 = Vs[VSW(k2*8+tg,   nt*8+g)];
                unsigned b1 = Vs[VSW(k2*8+tg+4, nt*8+g)];
                mma8(o[nt], pa, b0, b1);
            }
        }
        __syncthreads();
    }

    // epilogue: O /= l, write (B,T,D)
    float i0 = 1.f / lrow0, i1 = 1.f / lrow1;
    int b = bh >> 4, h = bh & 15;
    float* Op  = g_o + (size_t)(b*TSEQ + qrow0 + g)*DMODEL + h*64;
    float* Op8 = Op + (size_t)8*DMODEL;
    #pragma unroll
    for (int nt = 0; nt < 8; nt++){
        int d = nt*8 + 2*tg;
        Op [d]   = o[nt][0] * i0;
        Op [d+1] = o[nt][1] * i0;
        Op8[d]   = o[nt][2] * i1;
        Op8[d+1] = o[nt][3] * i1;
    }
}

extern "C" void kernel_launch(void* const* d_in, const int* in_sizes, int n_in,
                              void* d_out, int out_size)
{
    const float* x     = (const float*)d_in[0];
    const float* wqkv  = (const float*)d_in[1];
    const float* wproj = (const float*)d_in[2];
    const float* bproj = (const float*)d_in[3];
    float* out = (float*)d_out;

    gemm_tf32<3072, 0><<<dim3(24, 64), 256>>>(x, wqkv, nullptr, nullptr);
    attn_kernel<<<dim3(32, 64), 128>>>();
    gemm_tf32<1024, 1><<<dim3(8, 64), 256>>>(nullptr, wproj, bproj, out);
}

// round 4
// speedup vs baseline: 1.3031x; 1.3021x over previous
#include <cuda_runtime.h>
#include <math.h>
#include <stdint.h>

#define TSEQ 2048
#define NH 16
#define NB 4
#define DHD 64
#define BHT (NB*NH)          // 64
#define DMODEL 1024
#define MROWS (NB*TSEQ)      // 8192

// Scratch (device globals: allocation-free rule)
__device__ float g_q[BHT*TSEQ*DHD];
__device__ float g_k[BHT*TSEQ*DHD];
__device__ float g_v[BHT*TSEQ*DHD];
__device__ float g_o[MROWS*DMODEL];
__device__ float g_x[MROWS*DMODEL];        // rna-rounded x
__device__ float g_bqkv[3072*DMODEL];      // w_qkv^T, [N=3072][K=1024], rounded
__device__ float g_bproj[DMODEL*DMODEL];   // w_proj^T, [N=1024][K=1024], rounded

__device__ __forceinline__ unsigned f2t(float x){
    unsigned u; asm("cvt.rna.tf32.f32 %0, %1;" : "=r"(u) : "f"(x)); return u;
}
__device__ __forceinline__ float rnaf(float x){ return __uint_as_float(f2t(x)); }

__device__ __forceinline__ uint32_t smem_u32(const void* p){
    uint32_t a; asm("{ .reg .u64 t; cvta.to.shared.u64 t, %1; cvt.u32.u64 %0, t; }" : "=r"(a) : "l"(p));
    return a;
}
__device__ __forceinline__ void cpasync16(uint32_t s, const void* g){
    asm volatile("cp.async.cg.shared.global [%0], [%1], 16;" :: "r"(s), "l"(g));
}
__device__ __forceinline__ void cp_commit(){ asm volatile("cp.async.commit_group;" ::: "memory"); }
template<int N> __device__ __forceinline__ void cp_wait(){ asm volatile("cp.async.wait_group %0;" :: "n"(N) : "memory"); }

__device__ __forceinline__ void mma8(float* d, const unsigned* a, unsigned b0, unsigned b1){
    asm volatile("mma.sync.aligned.m16n8k8.row.col.f32.tf32.tf32.f32 "
        "{%0,%1,%2,%3},{%4,%5,%6,%7},{%8,%9},{%0,%1,%2,%3};"
        : "+f"(d[0]),"+f"(d[1]),"+f"(d[2]),"+f"(d[3])
        : "r"(a[0]),"r"(a[1]),"r"(a[2]),"r"(a[3]),"r"(b0),"r"(b1));
}

// ---------------- prep kernels ----------------
__global__ void round_x_kernel(const float* __restrict__ in, float* __restrict__ out){
    int i = blockIdx.x * blockDim.x + threadIdx.x;
    float4 v = ((const float4*)in)[i];
    v.x = rnaf(v.x); v.y = rnaf(v.y); v.z = rnaf(v.z); v.w = rnaf(v.w);
    ((float4*)out)[i] = v;
}

// src: R x C row-major -> dst: C x R row-major (values rna-rounded)
__global__ void transpose_round(const float* __restrict__ src, float* __restrict__ dst, int R, int C){
    __shared__ float t[32][33];
    int c0 = blockIdx.x * 32, r0 = blockIdx.y * 32;
    int x = threadIdx.x, y = threadIdx.y;     // block (32, 8)
    #pragma unroll
    for (int i = 0; i < 32; i += 8) t[y+i][x] = src[(size_t)(r0+y+i)*C + c0 + x];
    __syncthreads();
    #pragma unroll
    for (int i = 0; i < 32; i += 8) dst[(size_t)(c0+y+i)*R + r0 + x] = rnaf(t[x][y+i]);
}

// ---------------- GEMM: 128x128 CTA, 4 warps of 64x64, cp.async 3-stage, K-tile 32 ----------------
// A (M x 1024) row-major, Bt (N x 1024) row-major (i.e. B^T).  C = A * Bt^T.
// MODE 0: scatter into g_q/g_k/g_v head-major. MODE 1: + bias -> Cout. (MODE 1 reads A = g_o.)
// smem stage: A 128 rows x 144B, B 128 rows x 144B (32 tf32 + 16B pad). 3 stages = 110592 B.
#define GEMM_STAGE_B 36864
#define GEMM_SMEM (3*GEMM_STAGE_B)

template<int MODE>
__global__ __launch_bounds__(128, 2)
void gemm2(const float* __restrict__ A_, const float* __restrict__ Bt,
           const float* __restrict__ bias, float* __restrict__ Cout)
{
    extern __shared__ unsigned sm[];
    const int tid = threadIdx.x, warp = tid >> 5, lane = tid & 31;
    const int g = lane >> 2, tg = lane & 3;
    const int wm = (warp & 1) * 64, wn = (warp >> 1) * 64;
    const int row0 = blockIdx.y * 128, col0 = blockIdx.x * 128;
    const float* A = (MODE == 1) ? g_o : A_;

    float acc[4][8][4];
    #pragma unroll
    for (int mi = 0; mi < 4; mi++)
        #pragma unroll
        for (int ni = 0; ni < 8; ni++)
            #pragma unroll
            for (int e = 0; e < 4; e++) acc[mi][ni][e] = 0.f;

    const uint32_t sbase = smem_u32(sm);
    const int lr = tid >> 3, lc = tid & 7;     // 128 threads -> 16 rows x 8 chunks per pass

    auto load_stage = [&](int kt, int stg){
        uint32_t sA = sbase + stg * GEMM_STAGE_B;
        uint32_t sB = sA + 18432;
        const float* ga = A  + (size_t)(row0 + lr) * 1024 + kt * 32 + lc * 4;
        const float* gb = Bt + (size_t)(col0 + lr) * 1024 + kt * 32 + lc * 4;
        uint32_t so = lr * 144 + lc * 16;
        #pragma unroll
        for (int i = 0; i < 8; i++){              // 8 passes of 16 rows
            cpasync16(sA + so + i * (16*144), ga + (size_t)i * (16*1024));
            cpasync16(sB + so + i * (16*144), gb + (size_t)i * (16*1024));
        }
    };

    auto compute = [&](int stg){
        const unsigned* As = sm + stg * (GEMM_STAGE_B/4);
        const unsigned* Bs = As + 4608;
        #pragma unroll
        for (int ks = 0; ks < 4; ks++){
            const int k0 = ks * 8;
            unsigned af[4][4], bf[8][2];
            #pragma unroll
            for (int mi = 0; mi < 4; mi++){
                const unsigned* p = As + (wm + mi*16 + g) * 36 + k0 + tg;
                af[mi][0] = p[0];
                af[mi][1] = p[8*36];
                af[mi][2] = p[4];
                af[mi][3] = p[8*36 + 4];
            }
            #pragma unroll
            for (int ni = 0; ni < 8; ni++){
                const unsigned* p = Bs + (wn + ni*8 + g) * 36 + k0 + tg;
                bf[ni][0] = p[0];
                bf[ni][1] = p[4];
            }
            #pragma unroll
            for (int mi = 0; mi < 4; mi++)
                #pragma unroll
                for (int ni = 0; ni < 8; ni++)
                    mma8(acc[mi][ni], af[mi], bf[ni][0], bf[ni][1]);
        }
    };

    load_stage(0, 0); cp_commit();
    load_stage(1, 1); cp_commit();

    #pragma unroll 1
    for (int kt = 0; kt < 32; kt++){
        cp_wait<1>();
        __syncthreads();
        if (kt + 2 < 32) load_stage(kt + 2, (kt + 2) % 3);
        cp_commit();                    // uniform group counting (empty groups ok)
        compute(kt % 3);
    }

    // epilogue
    if (MODE == 0){
        const int colb = col0 + wn;               // 64-aligned -> single head
        const int part = colb >> 10;              // 0:q 1:k 2:v
        const int h = (colb & 1023) >> 6;
        float* dst0 = (part == 0) ? g_q : (part == 1) ? g_k : g_v;
        const int b = row0 >> 11;
        #pragma unroll
        for (int mi = 0; mi < 4; mi++){
            const int t = (row0 + wm + mi*16 + g) & 2047;
            float* p0 = dst0 + ((size_t)((b << 4) + h) * TSEQ + t) * DHD;
            float* p1 = p0 + 8 * DHD;
            #pragma unroll
            for (int ni = 0; ni < 8; ni++){
                const int d = ni*8 + 2*tg;
                *(float2*)(p0 + d) = make_float2(acc[mi][ni][0], acc[mi][ni][1]);
                *(float2*)(p1 + d) = make_float2(acc[mi][ni][2], acc[mi][ni][3]);
            }
        }
    } else {
        #pragma unroll
        for (int mi = 0; mi < 4; mi++){
            const int r = row0 + wm + mi*16 + g;
            #pragma unroll
            for (int ni = 0; ni < 8; ni++){
                const int c = col0 + wn + ni*8 + 2*tg;
                float2 bv = *(const float2*)(bias + c);
                *(float2*)(Cout + (size_t)r*1024 + c) =
                    make_float2(acc[mi][ni][0] + bv.x, acc[mi][ni][1] + bv.y);
                *(float2*)(Cout + (size_t)(r+8)*1024 + c) =
                    make_float2(acc[mi][ni][2] + bv.x, acc[mi][ni][3] + bv.y);
            }
        }
    }
}

// ---------------- attention (unchanged passing SIMT flash kernel) ----------------
#define KSW(r,c) ((r)*64 + ((c) ^ ((((r)&7))<<2)))
#define VSW(r,c) ((r)*64 + ((c) ^ ((((r)&3))<<3)))
#define PSW(r,c) ((r)*64 + ((c) ^ ((((r)&7))<<2)))

__global__ __launch_bounds__(128)
void attn_kernel()
{
    __shared__ unsigned Ks[64*64];
    __shared__ unsigned Vs[64*64];
    __shared__ unsigned Ps[64*64];

    const int qt = blockIdx.x, bh = blockIdx.y;
    const int tid = threadIdx.x, warp = tid >> 5, lane = tid & 31;
    const int g = lane >> 2, tg = lane & 3;
    const float* Qp = g_q + (size_t)bh * TSEQ * DHD;
    const float* Kp = g_k + (size_t)bh * TSEQ * DHD;
    const float* Vp = g_v + (size_t)bh * TSEQ * DHD;
    const int qrow0 = qt*64 + warp*16;

    unsigned qa[8][4];
    #pragma unroll
    for (int ks = 0; ks < 8; ks++){
        int d = ks*8;
        qa[ks][0] = f2t(Qp[(size_t)(qrow0+g  )*DHD + d+tg  ] * 0.125f);
        qa[ks][1] = f2t(Qp[(size_t)(qrow0+g+8)*DHD + d+tg  ] * 0.125f);
        qa[ks][2] = f2t(Qp[(size_t)(qrow0+g  )*DHD + d+tg+4] * 0.125f);
        qa[ks][3] = f2t(Qp[(size_t)(qrow0+g+8)*DHD + d+tg+4] * 0.125f);
    }

    float o[8][4];
    #pragma unroll
    for (int ni = 0; ni < 8; ni++){ o[ni][0]=0.f; o[ni][1]=0.f; o[ni][2]=0.f; o[ni][3]=0.f; }
    float mrow0 = -1e30f, mrow1 = -1e30f, lrow0 = 0.f, lrow1 = 0.f;

    for (int kt = 0; kt <= qt; ++kt){
        const int kb = kt * 64;
        #pragma unroll
        for (int i = 0; i < 8; i++){
            int v = tid + i*128;
            int r = v >> 4, c4 = v & 15;
            float4 kv = *(const float4*)&Kp[(size_t)(kb+r)*DHD + c4*4];
            uint4 uk; uk.x=f2t(kv.x); uk.y=f2t(kv.y); uk.z=f2t(kv.z); uk.w=f2t(kv.w);
            *(uint4*)&Ks[KSW(r, c4*4)] = uk;
            float4 vv = *(const float4*)&Vp[(size_t)(kb+r)*DHD + c4*4];
            uint4 uv; uv.x=f2t(vv.x); uv.y=f2t(vv.y); uv.z=f2t(vv.z); uv.w=f2t(vv.w);
            *(uint4*)&Vs[VSW(r, c4*4)] = uv;
        }
        __syncthreads();

        float s[8][4];
        #pragma unroll
        for (int nt = 0; nt < 8; nt++){ s[nt][0]=0.f; s[nt][1]=0.f; s[nt][2]=0.f; s[nt][3]=0.f; }
        #pragma unroll
        for (int ks = 0; ks < 8; ks++){
            #pragma unroll
            for (int nt = 0; nt < 8; nt++){
                unsigned b0 = Ks[KSW(nt*8+g, ks*8+tg  )];
                unsigned b1 = Ks[KSW(nt*8+g, ks*8+tg+4)];
                mma8(s[nt], qa[ks], b0, b1);
            }
        }

        if (kt == qt){
            const int rb = warp*16 + g;
            #pragma unroll
            for (int nt = 0; nt < 8; nt++){
                int c = nt*8 + 2*tg;
                if (c   > rb  ) s[nt][0] = -1e30f;
                if (c+1 > rb  ) s[nt][1] = -1e30f;
                if (c   > rb+8) s[nt][2] = -1e30f;
                if (c+1 > rb+8) s[nt][3] = -1e30f;
            }
        }

        float mx0 = -1e30f, mx1 = -1e30f;
        #pragma unroll
        for (int nt = 0; nt < 8; nt++){
            mx0 = fmaxf(mx0, fmaxf(s[nt][0], s[nt][1]));
            mx1 = fmaxf(mx1, fmaxf(s[nt][2], s[nt][3]));
        }
        mx0 = fmaxf(mx0, __shfl_xor_sync(0xffffffffu, mx0, 1));
        mx0 = fmaxf(mx0, __shfl_xor_sync(0xffffffffu, mx0, 2));
        mx1 = fmaxf(mx1, __shfl_xor_sync(0xffffffffu, mx1, 1));
        mx1 = fmaxf(mx1, __shfl_xor_sync(0xffffffffu, mx1, 2));
        float mn0 = fmaxf(mrow0, mx0), mn1 = fmaxf(mrow1, mx1);
        float sc0 = __expf(mrow0 - mn0), sc1 = __expf(mrow1 - mn1);

        const int pr0 = warp*16 + g, pr1 = pr0 + 8;
        float sum0 = 0.f, sum1 = 0.f;
        #pragma unroll
        for (int nt = 0; nt < 8; nt++){
            float p00 = __expf(s[nt][0] - mn0);
            float p01 = __expf(s[nt][1] - mn0);
            float p10 = __expf(s[nt][2] - mn1);
            float p11 = __expf(s[nt][3] - mn1);
            sum0 += p00 + p01; sum1 += p10 + p11;
            int c = nt*8 + 2*tg;
            Ps[PSW(pr0, c  )] = f2t(p00);
            Ps[PSW(pr0, c+1)] = f2t(p01);
            Ps[PSW(pr1, c  )] = f2t(p10);
            Ps[PSW(pr1, c+1)] = f2t(p11);
        }
        sum0 += __shfl_xor_sync(0xffffffffu, sum0, 1);
        sum0 += __shfl_xor_sync(0xffffffffu, sum0, 2);
        sum1 += __shfl_xor_sync(0xffffffffu, sum1, 1);
        sum1 += __shfl_xor_sync(0xffffffffu, sum1, 2);
        lrow0 = lrow0 * sc0 + sum0;
        lrow1 = lrow1 * sc1 + sum1;
        mrow0 = mn0; mrow1 = mn1;
        #pragma unroll
        for (int nt = 0; nt < 8; nt++){
            o[nt][0] *= sc0; o[nt][1] *= sc0;
            o[nt][2] *= sc1; o[nt][3] *= sc1;
        }
        __syncwarp();

        #pragma unroll
        for (int k2 = 0; k2 < 8; k2++){
            unsigned pa[4];
            pa[0] = Ps[PSW(pr0, k2*8+tg  )];
            pa[1] = Ps[PSW(pr1, k2*8+tg  )];
            pa[2] = Ps[PSW(pr0, k2*8+tg+4)];
            pa[3] = Ps[PSW(pr1, k2*8+tg+4)];
            #pragma unroll
            for (int nt = 0; nt < 8; nt++){
                unsigned b0 = Vs[VSW(k2*8+tg,   nt*8+g)];
                unsigned b1 = Vs[VSW(k2*8+tg+4, nt*8+g)];
                mma8(o[nt], pa, b0, b1);
            }
        }
        __syncthreads();
    }

    // epilogue: O /= l, rna-rounded (proj GEMM consumes pre-rounded tf32 values)
    float i0 = 1.f / lrow0, i1 = 1.f / lrow1;
    int b = bh >> 4, h = bh & 15;
    float* Op  = g_o + (size_t)(b*TSEQ + qrow0 + g)*DMODEL + h*64;
    float* Op8 = Op + (size_t)8*DMODEL;
    #pragma unroll
    for (int nt = 0; nt < 8; nt++){
        int d = nt*8 + 2*tg;
        Op [d]   = rnaf(o[nt][0] * i0);
        Op [d+1] = rnaf(o[nt][1] * i0);
        Op8[d]   = rnaf(o[nt][2] * i1);
        Op8[d+1] = rnaf(o[nt][3] * i1);
    }
}

extern "C" void kernel_launch(void* const* d_in, const int* in_sizes, int n_in,
                              void* d_out, int out_size)
{
    const float* x     = (const float*)d_in[0];
    const float* wqkv  = (const float*)d_in[1];
    const float* wproj = (const float*)d_in[2];
    const float* bproj = (const float*)d_in[3];
    float* out = (float*)d_out;

    cudaFuncSetAttribute(gemm2<0>, cudaFuncAttributeMaxDynamicSharedMemorySize, GEMM_SMEM);
    cudaFuncSetAttribute(gemm2<1>, cudaFuncAttributeMaxDynamicSharedMemorySize, GEMM_SMEM);

    float* px;  cudaGetSymbolAddress((void**)&px,  g_x);
    float* pbq; cudaGetSymbolAddress((void**)&pbq, g_bqkv);
    float* pbp; cudaGetSymbolAddress((void**)&pbp, g_bproj);

    round_x_kernel<<<MROWS*DMODEL/4/256, 256>>>(x, px);
    transpose_round<<<dim3(3072/32, 1024/32), dim3(32, 8)>>>(wqkv, pbq, 1024, 3072);
    transpose_round<<<dim3(1024/32, 1024/32), dim3(32, 8)>>>(wproj, pbp, 1024, 1024);

    gemm2<0><<<dim3(24, 64), 128, GEMM_SMEM>>>(px, pbq, nullptr, nullptr);
    attn_kernel<<<dim3(32, 64), 128>>>();
    gemm2<1><<<dim3(8, 64), 128, GEMM_SMEM>>>(nullptr, pbp, bproj, out);
}

// round 5
// speedup vs baseline: 1.4185x; 1.0885x over previous
#include <cuda_runtime.h>
#include <math.h>
#include <stdint.h>

#define TSEQ 2048
#define NH 16
#define NB 4
#define DHD 64
#define BHT (NB*NH)          // 64
#define DMODEL 1024
#define MROWS (NB*TSEQ)      // 8192

// Scratch (device globals: allocation-free rule)
__device__ float g_q[BHT*TSEQ*DHD];        // tf32-rna rounded by gemm epilogue
__device__ float g_k[BHT*TSEQ*DHD];        // rounded
__device__ float g_v[BHT*TSEQ*DHD];        // rounded
__device__ float g_o[MROWS*DMODEL];        // rounded by attn epilogue
__device__ float g_x[MROWS*DMODEL];        // rna-rounded x
__device__ float g_bqkv[3072*DMODEL];      // w_qkv^T, [N=3072][K=1024], rounded
__device__ float g_bproj[DMODEL*DMODEL];   // w_proj^T, [N=1024][K=1024], rounded

__device__ __forceinline__ unsigned f2t(float x){
    unsigned u; asm("cvt.rna.tf32.f32 %0, %1;" : "=r"(u) : "f"(x)); return u;
}
__device__ __forceinline__ float rnaf(float x){ return __uint_as_float(f2t(x)); }

__device__ __forceinline__ uint32_t smem_u32(const void* p){
    uint32_t a; asm("{ .reg .u64 t; cvta.to.shared.u64 t, %1; cvt.u32.u64 %0, t; }" : "=r"(a) : "l"(p));
    return a;
}
__device__ __forceinline__ void cpasync16(uint32_t s, const void* g){
    asm volatile("cp.async.cg.shared.global [%0], [%1], 16;" :: "r"(s), "l"(g));
}
__device__ __forceinline__ void cp_commit(){ asm volatile("cp.async.commit_group;" ::: "memory"); }
template<int N> __device__ __forceinline__ void cp_wait(){ asm volatile("cp.async.wait_group %0;" :: "n"(N) : "memory"); }

__device__ __forceinline__ void mma8(float* d, const unsigned* a, unsigned b0, unsigned b1){
    asm volatile("mma.sync.aligned.m16n8k8.row.col.f32.tf32.tf32.f32 "
        "{%0,%1,%2,%3},{%4,%5,%6,%7},{%8,%9},{%0,%1,%2,%3};"
        : "+f"(d[0]),"+f"(d[1]),"+f"(d[2]),"+f"(d[3])
        : "r"(a[0]),"r"(a[1]),"r"(a[2]),"r"(a[3]),"r"(b0),"r"(b1));
}

// ---------------- prep kernels ----------------
__global__ void round_x_kernel(const float* __restrict__ in, float* __restrict__ out){
    int i = blockIdx.x * blockDim.x + threadIdx.x;
    float4 v = ((const float4*)in)[i];
    v.x = rnaf(v.x); v.y = rnaf(v.y); v.z = rnaf(v.z); v.w = rnaf(v.w);
    ((float4*)out)[i] = v;
}

// src: R x C row-major -> dst: C x R row-major (values rna-rounded)
__global__ void transpose_round(const float* __restrict__ src, float* __restrict__ dst, int R, int C){
    __shared__ float t[32][33];
    int c0 = blockIdx.x * 32, r0 = blockIdx.y * 32;
    int x = threadIdx.x, y = threadIdx.y;     // block (32, 8)
    #pragma unroll
    for (int i = 0; i < 32; i += 8) t[y+i][x] = src[(size_t)(r0+y+i)*C + c0 + x];
    __syncthreads();
    #pragma unroll
    for (int i = 0; i < 32; i += 8) dst[(size_t)(c0+y+i)*R + r0 + x] = rnaf(t[x][y+i]);
}

// ---------------- GEMM: 128x128 CTA, 4 warps of 64x64, cp.async 3-stage, K-tile 32 ----------------
#define GEMM_STAGE_B 36864
#define GEMM_SMEM (3*GEMM_STAGE_B)

template<int MODE>
__global__ __launch_bounds__(128, 2)
void gemm2(const float* __restrict__ A_, const float* __restrict__ Bt,
           const float* __restrict__ bias, float* __restrict__ Cout)
{
    extern __shared__ unsigned sm[];
    const int tid = threadIdx.x, warp = tid >> 5, lane = tid & 31;
    const int g = lane >> 2, tg = lane & 3;
    const int wm = (warp & 1) * 64, wn = (warp >> 1) * 64;
    const int row0 = blockIdx.y * 128, col0 = blockIdx.x * 128;
    const float* A = (MODE == 1) ? g_o : A_;

    float acc[4][8][4];
    #pragma unroll
    for (int mi = 0; mi < 4; mi++)
        #pragma unroll
        for (int ni = 0; ni < 8; ni++)
            #pragma unroll
            for (int e = 0; e < 4; e++) acc[mi][ni][e] = 0.f;

    const uint32_t sbase = smem_u32(sm);
    const int lr = tid >> 3, lc = tid & 7;

    auto load_stage = [&](int kt, int stg){
        uint32_t sA = sbase + stg * GEMM_STAGE_B;
        uint32_t sB = sA + 18432;
        const float* ga = A  + (size_t)(row0 + lr) * 1024 + kt * 32 + lc * 4;
        const float* gb = Bt + (size_t)(col0 + lr) * 1024 + kt * 32 + lc * 4;
        uint32_t so = lr * 144 + lc * 16;
        #pragma unroll
        for (int i = 0; i < 8; i++){
            cpasync16(sA + so + i * (16*144), ga + (size_t)i * (16*1024));
            cpasync16(sB + so + i * (16*144), gb + (size_t)i * (16*1024));
        }
    };

    auto compute = [&](int stg){
        const unsigned* As = sm + stg * (GEMM_STAGE_B/4);
        const unsigned* Bs = As + 4608;
        #pragma unroll
        for (int ks = 0; ks < 4; ks++){
            const int k0 = ks * 8;
            unsigned af[4][4], bf[8][2];
            #pragma unroll
            for (int mi = 0; mi < 4; mi++){
                const unsigned* p = As + (wm + mi*16 + g) * 36 + k0 + tg;
                af[mi][0] = p[0];
                af[mi][1] = p[8*36];
                af[mi][2] = p[4];
                af[mi][3] = p[8*36 + 4];
            }
            #pragma unroll
            for (int ni = 0; ni < 8; ni++){
                const unsigned* p = Bs + (wn + ni*8 + g) * 36 + k0 + tg;
                bf[ni][0] = p[0];
                bf[ni][1] = p[4];
            }
            #pragma unroll
            for (int mi = 0; mi < 4; mi++)
                #pragma unroll
                for (int ni = 0; ni < 8; ni++)
                    mma8(acc[mi][ni], af[mi], bf[ni][0], bf[ni][1]);
        }
    };

    load_stage(0, 0); cp_commit();
    load_stage(1, 1); cp_commit();

    #pragma unroll 1
    for (int kt = 0; kt < 32; kt++){
        cp_wait<1>();
        __syncthreads();
        if (kt + 2 < 32) load_stage(kt + 2, (kt + 2) % 3);
        cp_commit();
        compute(kt % 3);
    }

    // epilogue
    if (MODE == 0){
        // store tf32-rna rounded values: attention consumes raw bytes via cp.async
        const int colb = col0 + wn;
        const int part = colb >> 10;
        const int h = (colb & 1023) >> 6;
        float* dst0 = (part == 0) ? g_q : (part == 1) ? g_k : g_v;
        const int b = row0 >> 11;
        #pragma unroll
        for (int mi = 0; mi < 4; mi++){
            const int t = (row0 + wm + mi*16 + g) & 2047;
            float* p0 = dst0 + ((size_t)((b << 4) + h) * TSEQ + t) * DHD;
            float* p1 = p0 + 8 * DHD;
            #pragma unroll
            for (int ni = 0; ni < 8; ni++){
                const int d = ni*8 + 2*tg;
                *(float2*)(p0 + d) = make_float2(rnaf(acc[mi][ni][0]), rnaf(acc[mi][ni][1]));
                *(float2*)(p1 + d) = make_float2(rnaf(acc[mi][ni][2]), rnaf(acc[mi][ni][3]));
            }
        }
    } else {
        #pragma unroll
        for (int mi = 0; mi < 4; mi++){
            const int r = row0 + wm + mi*16 + g;
            #pragma unroll
            for (int ni = 0; ni < 8; ni++){
                const int c = col0 + wn + ni*8 + 2*tg;
                float2 bv = *(const float2*)(bias + c);
                *(float2*)(Cout + (size_t)r*1024 + c) =
                    make_float2(acc[mi][ni][0] + bv.x, acc[mi][ni][1] + bv.y);
                *(float2*)(Cout + (size_t)(r+8)*1024 + c) =
                    make_float2(acc[mi][ni][2] + bv.x, acc[mi][ni][3] + bv.y);
            }
        }
    }
}

// ---------------- attention: cp.async pipelined K (double) / V (single) ----------------
#define KSW(r,c) ((r)*64 + ((c) ^ ((((r)&7))<<2)))
#define VSW(r,c) ((r)*64 + ((c) ^ ((((r)&3))<<3)))
#define PSW(r,c) ((r)*64 + ((c) ^ ((((r)&7))<<2)))

// dynamic smem layout (unsigned units): K0 @0, K1 @4096, V @8192, P @12288 (64KB)
#define ATTN_SMEM 65536

__global__ __launch_bounds__(128)
void attn_kernel()
{
    extern __shared__ unsigned smA[];
    unsigned* Vs = smA + 8192;
    unsigned* Ps = smA + 12288;

    const int qt = blockIdx.x, bh = blockIdx.y;
    const int tid = threadIdx.x, warp = tid >> 5, lane = tid & 31;
    const int g = lane >> 2, tg = lane & 3;
    const float* Qp = g_q + (size_t)bh * TSEQ * DHD;
    const float* Kp = g_k + (size_t)bh * TSEQ * DHD;
    const float* Vp = g_v + (size_t)bh * TSEQ * DHD;
    const int qrow0 = qt*64 + warp*16;
    const uint32_t sbase = smem_u32(smA);

    // per-thread chunk coords for tile loads (8 x 16B chunks per tensor)
    const int cr = tid >> 4, cc4 = (tid & 15) * 4;

    auto ld_k = [&](int kt, int buf){
        const float* src = Kp + (size_t)kt*64*DHD + cr*DHD + cc4;
        uint32_t db = sbase + buf*16384;
        #pragma unroll
        for (int i = 0; i < 8; i++)
            cpasync16(db + 4u*KSW(cr + i*8, cc4), src + (size_t)i*8*DHD);
    };
    auto ld_v = [&](int kt){
        const float* src = Vp + (size_t)kt*64*DHD + cr*DHD + cc4;
        uint32_t db = sbase + 32768;
        #pragma unroll
        for (int i = 0; i < 8; i++)
            cpasync16(db + 4u*VSW(cr + i*8, cc4), src + (size_t)i*8*DHD);
    };

    // Q fragments: values pre-rounded to tf32 by gemm epilogue; *0.125 is exact
    unsigned qa[8][4];
    #pragma unroll
    for (int ks = 0; ks < 8; ks++){
        int d = ks*8;
        qa[ks][0] = __float_as_uint(Qp[(size_t)(qrow0+g  )*DHD + d+tg  ] * 0.125f);
        qa[ks][1] = __float_as_uint(Qp[(size_t)(qrow0+g+8)*DHD + d+tg  ] * 0.125f);
        qa[ks][2] = __float_as_uint(Qp[(size_t)(qrow0+g  )*DHD + d+tg+4] * 0.125f);
        qa[ks][3] = __float_as_uint(Qp[(size_t)(qrow0+g+8)*DHD + d+tg+4] * 0.125f);
    }

    float o[8][4];
    #pragma unroll
    for (int ni = 0; ni < 8; ni++){ o[ni][0]=0.f; o[ni][1]=0.f; o[ni][2]=0.f; o[ni][3]=0.f; }
    float mrow0 = -1e30f, mrow1 = -1e30f, lrow0 = 0.f, lrow1 = 0.f;

    ld_k(0, 0); cp_commit();

    #pragma unroll 1
    for (int kt = 0; kt <= qt; ++kt){
        __syncthreads();                    // A: prev tile's smem reads complete
        ld_v(kt); cp_commit();
        if (kt < qt) ld_k(kt + 1, (kt + 1) & 1);
        cp_commit();                        // uniform 2 groups/iter
        cp_wait<2>();                       // K(kt) landed
        __syncthreads();                    // B: visible to all

        const unsigned* Ks = smA + (kt & 1) * 4096;

        // S = Q K^T
        float s[8][4];
        #pragma unroll
        for (int nt = 0; nt < 8; nt++){ s[nt][0]=0.f; s[nt][1]=0.f; s[nt][2]=0.f; s[nt][3]=0.f; }
        #pragma unroll
        for (int ks = 0; ks < 8; ks++){
            #pragma unroll
            for (int nt = 0; nt < 8; nt++){
                unsigned b0 = Ks[KSW(nt*8+g, ks*8+tg  )];
                unsigned b1 = Ks[KSW(nt*8+g, ks*8+tg+4)];
                mma8(s[nt], qa[ks], b0, b1);
            }
        }

        if (kt == qt){
            const int rb = warp*16 + g;
            #pragma unroll
            for (int nt = 0; nt < 8; nt++){
                int c = nt*8 + 2*tg;
                if (c   > rb  ) s[nt][0] = -1e30f;
                if (c+1 > rb  ) s[nt][1] = -1e30f;
                if (c   > rb+8) s[nt][2] = -1e30f;
                if (c+1 > rb+8) s[nt][3] = -1e30f;
            }
        }

        // online softmax (rows g, g+8)
        float mx0 = -1e30f, mx1 = -1e30f;
        #pragma unroll
        for (int nt = 0; nt < 8; nt++){
            mx0 = fmaxf(mx0, fmaxf(s[nt][0], s[nt][1]));
            mx1 = fmaxf(mx1, fmaxf(s[nt][2], s[nt][3]));
        }
        mx0 = fmaxf(mx0, __shfl_xor_sync(0xffffffffu, mx0, 1));
        mx0 = fmaxf(mx0, __shfl_xor_sync(0xffffffffu, mx0, 2));
        mx1 = fmaxf(mx1, __shfl_xor_sync(0xffffffffu, mx1, 1));
        mx1 = fmaxf(mx1, __shfl_xor_sync(0xffffffffu, mx1, 2));
        float mn0 = fmaxf(mrow0, mx0), mn1 = fmaxf(mrow1, mx1);
        float sc0 = __expf(mrow0 - mn0), sc1 = __expf(mrow1 - mn1);

        const int pr0 = warp*16 + g, pr1 = pr0 + 8;
        float sum0 = 0.f, sum1 = 0.f;
        #pragma unroll
        for (int nt = 0; nt < 8; nt++){
            float p00 = __expf(s[nt][0] - mn0);
            float p01 = __expf(s[nt][1] - mn0);
            float p10 = __expf(s[nt][2] - mn1);
            float p11 = __expf(s[nt][3] - mn1);
            sum0 += p00 + p01; sum1 += p10 + p11;
            int c = nt*8 + 2*tg;
            Ps[PSW(pr0, c  )] = f2t(p00);
            Ps[PSW(pr0, c+1)] = f2t(p01);
            Ps[PSW(pr1, c  )] = f2t(p10);
            Ps[PSW(pr1, c+1)] = f2t(p11);
        }
        sum0 += __shfl_xor_sync(0xffffffffu, sum0, 1);
        sum0 += __shfl_xor_sync(0xffffffffu, sum0, 2);
        sum1 += __shfl_xor_sync(0xffffffffu, sum1, 1);
        sum1 += __shfl_xor_sync(0xffffffffu, sum1, 2);
        lrow0 = lrow0 * sc0 + sum0;
        lrow1 = lrow1 * sc1 + sum1;
        mrow0 = mn0; mrow1 = mn1;
        #pragma unroll
        for (int nt = 0; nt < 8; nt++){
            o[nt][0] *= sc0; o[nt][1] *= sc0;
            o[nt][2] *= sc1; o[nt][3] *= sc1;
        }

        cp_wait<1>();                       // V(kt) landed (K(kt+1) may continue)
        __syncthreads();                    // C: V visible to all

        // O += P V
        #pragma unroll
        for (int k2 = 0; k2 < 8; k2++){
            unsigned pa[4];
            pa[0] = Ps[PSW(pr0, k2*8+tg  )];
            pa[1] = Ps[PSW(pr1, k2*8+tg  )];
            pa[2] = Ps[PSW(pr0, k2*8+tg+4)];
            pa[3] = Ps[PSW(pr1, k2*8+tg+4)];
            #pragma unroll
            for (int nt = 0; nt < 8; nt++){
                unsigned b0 = Vs[VSW(k2*8+tg,   nt*8+g)];
                unsigned b1 = Vs[VSW(k2*8+tg+4, nt*8+g)];
                mma8(o[nt], pa, b0, b1);
            }
        }
    }

    // epilogue: O /= l, rna-rounded (proj GEMM consumes pre-rounded tf32 values)
    float i0 = 1.f / lrow0, i1 = 1.f / lrow1;
    int b = bh >> 4, h = bh & 15;
    float* Op  = g_o + (size_t)(b*TSEQ + qrow0 + g)*DMODEL + h*64;
    float* Op8 = Op + (size_t)8*DMODEL;
    #pragma unroll
    for (int nt = 0; nt < 8; nt++){
        int d = nt*8 + 2*tg;
        Op [d]   = rnaf(o[nt][0] * i0);
        Op [d+1] = rnaf(o[nt][1] * i0);
        Op8[d]   = rnaf(o[nt][2] * i1);
        Op8[d+1] = rnaf(o[nt][3] * i1);
    }
}

extern "C" void kernel_launch(void* const* d_in, const int* in_sizes, int n_in,
                              void* d_out, int out_size)
{
    const float* x     = (const float*)d_in[0];
    const float* wqkv  = (const float*)d_in[1];
    const float* wproj = (const float*)d_in[2];
    const float* bproj = (const float*)d_in[3];
    float* out = (float*)d_out;

    cudaFuncSetAttribute(gemm2<0>, cudaFuncAttributeMaxDynamicSharedMemorySize, GEMM_SMEM);
    cudaFuncSetAttribute(gemm2<1>, cudaFuncAttributeMaxDynamicSharedMemorySize, GEMM_SMEM);
    cudaFuncSetAttribute(attn_kernel, cudaFuncAttributeMaxDynamicSharedMemorySize, ATTN_SMEM);

    float* px;  cudaGetSymbolAddress((void**)&px,  g_x);
    float* pbq; cudaGetSymbolAddress((void**)&pbq, g_bqkv);
    float* pbp; cudaGetSymbolAddress((void**)&pbp, g_bproj);

    round_x_kernel<<<MROWS*DMODEL/4/256, 256>>>(x, px);
    transpose_round<<<dim3(3072/32, 1024/32), dim3(32, 8)>>>(wqkv, pbq, 1024, 3072);
    transpose_round<<<dim3(1024/32, 1024/32), dim3(32, 8)>>>(wproj, pbp, 1024, 1024);

    gemm2<0><<<dim3(24, 64), 128, GEMM_SMEM>>>(px, pbq, nullptr, nullptr);
    attn_kernel<<<dim3(32, 64), 128, ATTN_SMEM>>>();
    gemm2<1><<<dim3(8, 64), 128, GEMM_SMEM>>>(nullptr, pbp, bproj, out);
}